// round 12
// baseline (speedup 1.0000x reference)
#include <cuda_runtime.h>
#include <cuda_fp16.h>

// x (B,N,1) f32, indices (2,NNZ) i32, values (NNZ,) f32, bias (M,1) f32
//   -> out (B,M,1) f32
#define NN   100000
#define MM   100000
#define NNZ  3200000
#define BB   32
#define NF4  (NN / 4)          // 25000 float4 per batch row
#define MF4  (MM / 4)

// xt: transposed activations in FP16, row n = 32 halfs = 64B = 8 uint2.
// uint2 element q of row n packs batches [4q, 4q+3] as two __half2.
__device__ uint2 g_xt[(size_t)NN * 8];
// yt: f32 accumulator (M, B), zeroed each call, RED.v4 target.
__device__ float g_yt[(size_t)MM * BB];

// ---------------------------------------------------------------------------
// Kernel 1: transpose x (B,N) f32 -> xt (N,B) fp16, zero yt (f32).
// Tile: 32 b-rows x 128 n-cols, float4 global loads, 256 threads.
// ---------------------------------------------------------------------------
__global__ void k_transpose_in(const float* __restrict__ x) {
    __shared__ float tile[128][33];
    const int tid = threadIdx.x;
    const int c4_base = blockIdx.x * 32;       // float4 column base
    const int n0 = c4_base * 4;                // element column base

    // Load: thread owns b = tid>>3, float4 column c4 = (tid&7) + 8i.
    const int b_ld  = tid >> 3;
    const int c4_lo = tid & 7;
    #pragma unroll
    for (int i = 0; i < 4; i++) {
        const int c4l = c4_lo + 8 * i;                 // 0..31 within tile
        const int c4g = c4_base + c4l;
        if (c4g < NF4) {
            const float4 v =
                reinterpret_cast<const float4*>(x)[(size_t)b_ld * NF4 + c4g];
            tile[4 * c4l + 0][b_ld] = v.x;
            tile[4 * c4l + 1][b_ld] = v.y;
            tile[4 * c4l + 2][b_ld] = v.z;
            tile[4 * c4l + 3][b_ld] = v.w;
        }
    }
    __syncthreads();

    // Store: thread owns n_local = (tid>>3) + 32i, batch-quad b4 = tid&7.
    const int b4 = tid & 7;
    #pragma unroll
    for (int i = 0; i < 4; i++) {
        const int nl = (tid >> 3) + 32 * i;            // 0..127
        const int n  = n0 + nl;
        if (n < NN) {
            // Pack batches [4*b4 .. 4*b4+3] as two half2 -> uint2 (8B).
            __half2 p0 = __floats2half2_rn(tile[nl][4 * b4 + 0],
                                           tile[nl][4 * b4 + 1]);
            __half2 p1 = __floats2half2_rn(tile[nl][4 * b4 + 2],
                                           tile[nl][4 * b4 + 3]);
            uint2 u;
            u.x = *reinterpret_cast<const unsigned int*>(&p0);
            u.y = *reinterpret_cast<const unsigned int*>(&p1);
            g_xt[(size_t)n * 8 + b4] = u;
            // Zero the f32 accumulator (NN == MM, same guard).
            reinterpret_cast<float4*>(g_yt)[(size_t)n * 8 + b4] =
                make_float4(0.f, 0.f, 0.f, 0.f);
        }
    }
}

// ---------------------------------------------------------------------------
// Kernel 2: edge scatter. 8 threads per edge (proven config). Each thread:
// one 8B gather (4 fp16 batches), convert to f32, one red.global.add.v4.f32.
// Gather per edge: 64B contiguous (2 sectors) instead of 128B.
// ---------------------------------------------------------------------------
__global__ void k_scatter(const int* __restrict__ indices,
                          const float* __restrict__ values) {
    const long long t = (long long)blockIdx.x * blockDim.x + threadIdx.x;
    const long long e = t >> 3;        // edge id
    const int       q = (int)(t & 7);  // which batch-quad
    if (e >= NNZ) return;

    const int   src = indices[e];
    const int   dst = indices[(long long)NNZ + e];
    const float v   = values[e];

    const uint2 u = g_xt[(size_t)src * 8 + q];
    const __half2 h0 = *reinterpret_cast<const __half2*>(&u.x);
    const __half2 h1 = *reinterpret_cast<const __half2*>(&u.y);
    const float2 f0 = __half22float2(h0);
    const float2 f1 = __half22float2(h1);

    float4* p = reinterpret_cast<float4*>(g_yt) + (size_t)dst * 8 + q;
    asm volatile("red.global.add.v4.f32 [%0], {%1, %2, %3, %4};"
                 :: "l"(p), "f"(v * f0.x), "f"(v * f0.y),
                    "f"(v * f1.x), "f"(v * f1.y)
                 : "memory");
}

// ---------------------------------------------------------------------------
// Kernel 3: transpose yt (M,B) f32 -> out (B,M) + bias. (Unchanged from R10:
// the improved component.) Tile 128 m x 32 b, float4 both sides.
// ---------------------------------------------------------------------------
__global__ void k_transpose_out(float* __restrict__ out,
                                const float* __restrict__ bias) {
    __shared__ float tile[32][129];
    const int tid = threadIdx.x;
    const int m0 = blockIdx.x * 128;

    const int b4 = tid & 7;
    #pragma unroll
    for (int i = 0; i < 4; i++) {
        const int ml = (tid >> 3) + 32 * i;            // 0..127
        const int m  = m0 + ml;
        if (m < MM) {
            const float4 v =
                reinterpret_cast<const float4*>(g_yt)[(size_t)m * 8 + b4];
            tile[4 * b4 + 0][ml] = v.x;
            tile[4 * b4 + 1][ml] = v.y;
            tile[4 * b4 + 2][ml] = v.z;
            tile[4 * b4 + 3][ml] = v.w;
        }
    }
    __syncthreads();

    const int b_st  = tid >> 3;
    const int m4_lo = tid & 7;
    #pragma unroll
    for (int i = 0; i < 4; i++) {
        const int m4l = m4_lo + 8 * i;                 // float4 idx within tile
        const int m4g = (m0 >> 2) + m4l;
        if (m4g < MF4) {
            const int me = 4 * m4l;
            const float4 bv = reinterpret_cast<const float4*>(bias)[m4g];
            float4 r;
            r.x = tile[b_st][me + 0] + bv.x;
            r.y = tile[b_st][me + 1] + bv.y;
            r.z = tile[b_st][me + 2] + bv.z;
            r.w = tile[b_st][me + 3] + bv.w;
            reinterpret_cast<float4*>(out)[(size_t)b_st * MF4 + m4g] = r;
        }
    }
}

extern "C" void kernel_launch(void* const* d_in, const int* in_sizes, int n_in,
                              void* d_out, int out_size) {
    const float* x       = (const float*)d_in[0];   // (B, N, 1)
    const int*   indices = (const int*)  d_in[1];   // (2, NNZ)
    const float* values  = (const float*)d_in[2];   // (NNZ,)
    const float* bias    = (const float*)d_in[3];   // (M, 1)
    float*       out     = (float*)d_out;           // (B, M, 1)

    (void)in_sizes; (void)n_in; (void)out_size;

    {   // 1) transpose x -> xt (fp16), zero yt
        const int blocks = (NF4 + 31) / 32;            // 782
        k_transpose_in<<<blocks, 256>>>(x);
    }
    {   // 2) edge scatter: NNZ * 8 threads
        const long long total = (long long)NNZ * 8;
        const int threads = 256;
        const int blocks = (int)((total + threads - 1) / threads);
        k_scatter<<<blocks, threads>>>(indices, values);
    }
    {   // 3) transpose yt -> out (+bias)
        const int blocks = (MF4 + 31) / 32;            // 782
        k_transpose_out<<<blocks, 256>>>(out, bias);
    }
}

// round 13
// speedup vs baseline: 1.3835x; 1.3835x over previous
#include <cuda_runtime.h>

// x (B,N,1) f32, indices (2,NNZ) i32, values (NNZ,) f32, bias (M,1) f32
//   -> out (B,M,1) f32
#define NN   100000
#define MM   100000
#define NNZ  3200000
#define BB   32
#define NF4  (NN / 4)          // 25000 float4 per batch row
#define MF4  (MM / 4)

// Scratch in batch-contiguous layout:
// xt[n*32 + b] = x[b*N + n];  yt[m*32 + b] starts at bias[m], RED-accumulated,
// then transposed out.
__device__ float g_xt[(size_t)NN * BB];
__device__ float g_yt[(size_t)MM * BB];

// ---------------------------------------------------------------------------
// Kernel 1: transpose x (B,N) -> xt (N,B); init yt[m][*] = bias[m].
// Tile: 32 b-rows x 128 n-cols, float4 global accesses, 256 threads.
// ---------------------------------------------------------------------------
__global__ void k_transpose_in(const float* __restrict__ x,
                               const float* __restrict__ bias) {
    __shared__ float tile[128][33];
    const int tid = threadIdx.x;
    const int c4_base = blockIdx.x * 32;       // float4 column base
    const int n0 = c4_base * 4;                // element column base

    // Load phase: thread owns b = tid>>3, float4 column c4 = (tid&7) + 8i.
    const int b_ld  = tid >> 3;
    const int c4_lo = tid & 7;
    #pragma unroll
    for (int i = 0; i < 4; i++) {
        const int c4l = c4_lo + 8 * i;                 // 0..31 within tile
        const int c4g = c4_base + c4l;
        if (c4g < NF4) {
            const float4 v =
                reinterpret_cast<const float4*>(x)[(size_t)b_ld * NF4 + c4g];
            tile[4 * c4l + 0][b_ld] = v.x;
            tile[4 * c4l + 1][b_ld] = v.y;
            tile[4 * c4l + 2][b_ld] = v.z;
            tile[4 * c4l + 3][b_ld] = v.w;
        }
    }
    __syncthreads();

    // Store phase: thread owns n_local = (tid>>3) + 32i, batch-quad b4 = tid&7.
    const int b4 = tid & 7;
    #pragma unroll
    for (int i = 0; i < 4; i++) {
        const int nl = (tid >> 3) + 32 * i;            // 0..127
        const int n  = n0 + nl;
        if (n < NN) {
            float4 v;
            v.x = tile[nl][4 * b4 + 0];
            v.y = tile[nl][4 * b4 + 1];
            v.z = tile[nl][4 * b4 + 2];
            v.w = tile[nl][4 * b4 + 3];
            reinterpret_cast<float4*>(g_xt)[(size_t)n * 8 + b4] = v;
            // yt row n starts at bias[n] in every batch slot (NN == MM).
            const float bv = bias[n];                  // broadcast across b4
            reinterpret_cast<float4*>(g_yt)[(size_t)n * 8 + b4] =
                make_float4(bv, bv, bv, bv);
        }
    }
}

// ---------------------------------------------------------------------------
// Kernel 2: edge scatter — EXACT R3/R9/R10 structure (best measured; three
// alternative shapes all regressed). 8 threads per edge; one coalesced 128B
// float4 gather from xt, one red.global.add.v4.f32 into yt.
// ---------------------------------------------------------------------------
__global__ void k_scatter(const int* __restrict__ indices,
                          const float* __restrict__ values) {
    const long long t = (long long)blockIdx.x * blockDim.x + threadIdx.x;
    const long long e = t >> 3;        // edge id
    const int       q = (int)(t & 7);  // which float4 of the 32 batches
    if (e >= NNZ) return;

    const int   src = indices[e];
    const int   dst = indices[(long long)NNZ + e];
    const float v   = values[e];

    const float4 xv = reinterpret_cast<const float4*>(g_xt)[(size_t)src * 8 + q];
    const float4 c  = make_float4(v * xv.x, v * xv.y, v * xv.z, v * xv.w);

    float4* p = reinterpret_cast<float4*>(g_yt) + (size_t)dst * 8 + q;
    asm volatile("red.global.add.v4.f32 [%0], {%1, %2, %3, %4};"
                 :: "l"(p), "f"(c.x), "f"(c.y), "f"(c.z), "f"(c.w)
                 : "memory");
}

// ---------------------------------------------------------------------------
// Kernel 3: transpose yt (M,B) -> out (B,M). Bias already folded into yt.
// Tile: 128 m-rows x 32 b-cols; smem tile[b][m_local], pitch 129.
// ---------------------------------------------------------------------------
__global__ void k_transpose_out(float* __restrict__ out) {
    __shared__ float tile[32][129];
    const int tid = threadIdx.x;
    const int m0 = blockIdx.x * 128;

    // Load phase: thread owns m_local = (tid>>3) + 32i, b4 = tid&7.
    const int b4 = tid & 7;
    #pragma unroll
    for (int i = 0; i < 4; i++) {
        const int ml = (tid >> 3) + 32 * i;            // 0..127
        const int m  = m0 + ml;
        if (m < MM) {
            const float4 v =
                reinterpret_cast<const float4*>(g_yt)[(size_t)m * 8 + b4];
            tile[4 * b4 + 0][ml] = v.x;
            tile[4 * b4 + 1][ml] = v.y;
            tile[4 * b4 + 2][ml] = v.z;
            tile[4 * b4 + 3][ml] = v.w;
        }
    }
    __syncthreads();

    // Store phase: thread owns b = tid>>3, m4 = (tid&7) + 8i.
    const int b_st  = tid >> 3;
    const int m4_lo = tid & 7;
    #pragma unroll
    for (int i = 0; i < 4; i++) {
        const int m4l = m4_lo + 8 * i;                 // float4 idx within tile
        const int m4g = (m0 >> 2) + m4l;
        if (m4g < MF4) {
            const int me = 4 * m4l;
            float4 r;
            r.x = tile[b_st][me + 0];
            r.y = tile[b_st][me + 1];
            r.z = tile[b_st][me + 2];
            r.w = tile[b_st][me + 3];
            reinterpret_cast<float4*>(out)[(size_t)b_st * MF4 + m4g] = r;
        }
    }
}

extern "C" void kernel_launch(void* const* d_in, const int* in_sizes, int n_in,
                              void* d_out, int out_size) {
    const float* x       = (const float*)d_in[0];   // (B, N, 1)
    const int*   indices = (const int*)  d_in[1];   // (2, NNZ)
    const float* values  = (const float*)d_in[2];   // (NNZ,)
    const float* bias    = (const float*)d_in[3];   // (M, 1)
    float*       out     = (float*)d_out;           // (B, M, 1)

    (void)in_sizes; (void)n_in; (void)out_size;

    {   // 1) transpose x -> xt, init yt = bias
        const int blocks = (NF4 + 31) / 32;            // 782
        k_transpose_in<<<blocks, 256>>>(x, bias);
    }
    {   // 2) edge scatter: NNZ * 8 threads (proven config, untouched)
        const long long total = (long long)NNZ * 8;
        const int threads = 256;
        const int blocks = (int)((total + threads - 1) / threads);
        k_scatter<<<blocks, threads>>>(indices, values);
    }
    {   // 3) transpose yt -> out
        const int blocks = (MF4 + 31) / 32;            // 782
        k_transpose_out<<<blocks, 256>>>(out);
    }
}

// round 14
// speedup vs baseline: 1.4314x; 1.0346x over previous
#include <cuda_runtime.h>

// x (B,N,1) f32, indices (2,NNZ) i32, values (NNZ,) f32, bias (M,1) f32
//   -> out (B,M,1) f32
#define NN   100000
#define MM   100000
#define NNZ  3200000
#define BB   32
#define NF4  (NN / 4)          // 25000 float4 per batch row
#define MF4  (MM / 4)

// Scratch in batch-contiguous layout:
// xt[n*32 + b] = x[b*N + n];  yt[m*32 + b] accumulates, then transposed out.
__device__ float g_xt[(size_t)NN * BB];
__device__ float g_yt[(size_t)MM * BB];

// ---------------------------------------------------------------------------
// Kernel 1: transpose x (B,N) -> xt (N,B), zero yt. float4 on both global
// sides. Tile: 32 b-rows x 128 n-cols. 256 threads.
// ---------------------------------------------------------------------------
__global__ void k_transpose_in(const float* __restrict__ x) {
    __shared__ float tile[128][33];
    const int tid = threadIdx.x;
    const int c4_base = blockIdx.x * 32;       // float4 column base
    const int n0 = c4_base * 4;                // element column base

    // Load phase: thread owns b = tid>>3, float4 column c4 = (tid&7) + 8i.
    const int b_ld  = tid >> 3;
    const int c4_lo = tid & 7;
    #pragma unroll
    for (int i = 0; i < 4; i++) {
        const int c4l = c4_lo + 8 * i;                 // 0..31 within tile
        const int c4g = c4_base + c4l;
        if (c4g < NF4) {
            const float4 v =
                reinterpret_cast<const float4*>(x)[(size_t)b_ld * NF4 + c4g];
            tile[4 * c4l + 0][b_ld] = v.x;
            tile[4 * c4l + 1][b_ld] = v.y;
            tile[4 * c4l + 2][b_ld] = v.z;
            tile[4 * c4l + 3][b_ld] = v.w;
        }
    }
    __syncthreads();

    // Store phase: thread owns n_local = (tid>>3) + 32i, batch-quad b4 = tid&7.
    const int b4 = tid & 7;
    #pragma unroll
    for (int i = 0; i < 4; i++) {
        const int nl = (tid >> 3) + 32 * i;            // 0..127
        const int n  = n0 + nl;
        if (n < NN) {
            float4 v;
            v.x = tile[nl][4 * b4 + 0];
            v.y = tile[nl][4 * b4 + 1];
            v.z = tile[nl][4 * b4 + 2];
            v.w = tile[nl][4 * b4 + 3];
            reinterpret_cast<float4*>(g_xt)[(size_t)n * 8 + b4] = v;
            reinterpret_cast<float4*>(g_yt)[(size_t)n * 8 + b4] =
                make_float4(0.f, 0.f, 0.f, 0.f);
        }
    }
}

// ---------------------------------------------------------------------------
// Kernel 2: edge scatter — the proven optimum (R3/R9/R10; five alternative
// shapes regressed). 8 threads per edge; one coalesced 128B float4 gather
// from xt, one red.global.add.v4.f32 into yt. Grid exact: NNZ*8 threads ==
// 100000 blocks * 256, so no bounds guard needed.
// ---------------------------------------------------------------------------
__global__ void k_scatter(const int* __restrict__ indices,
                          const float* __restrict__ values) {
    const long long t = (long long)blockIdx.x * blockDim.x + threadIdx.x;
    const long long e = t >> 3;        // edge id (< NNZ by construction)
    const int       q = (int)(t & 7);  // which float4 of the 32 batches

    const int   src = indices[e];
    const int   dst = indices[(long long)NNZ + e];
    const float v   = values[e];

    const float4 xv = reinterpret_cast<const float4*>(g_xt)[(size_t)src * 8 + q];
    const float4 c  = make_float4(v * xv.x, v * xv.y, v * xv.z, v * xv.w);

    float4* p = reinterpret_cast<float4*>(g_yt) + (size_t)dst * 8 + q;
    asm volatile("red.global.add.v4.f32 [%0], {%1, %2, %3, %4};"
                 :: "l"(p), "f"(c.x), "f"(c.y), "f"(c.z), "f"(c.w)
                 : "memory");
}

// ---------------------------------------------------------------------------
// Kernel 3: transpose yt (M,B) -> out (B,M) + bias. float4 both sides.
// Tile: 128 m-rows x 32 b-cols; smem tile[b][m_local], pitch 129.
// ---------------------------------------------------------------------------
__global__ void k_transpose_out(float* __restrict__ out,
                                const float* __restrict__ bias) {
    __shared__ float tile[32][129];
    const int tid = threadIdx.x;
    const int m0 = blockIdx.x * 128;

    // Load phase: thread owns m_local = (tid>>3) + 32i, b4 = tid&7.
    const int b4 = tid & 7;
    #pragma unroll
    for (int i = 0; i < 4; i++) {
        const int ml = (tid >> 3) + 32 * i;            // 0..127
        const int m  = m0 + ml;
        if (m < MM) {
            const float4 v =
                reinterpret_cast<const float4*>(g_yt)[(size_t)m * 8 + b4];
            tile[4 * b4 + 0][ml] = v.x;
            tile[4 * b4 + 1][ml] = v.y;
            tile[4 * b4 + 2][ml] = v.z;
            tile[4 * b4 + 3][ml] = v.w;
        }
    }
    __syncthreads();

    // Store phase: thread owns b = tid>>3, m4 = (tid&7) + 8i.
    const int b_st  = tid >> 3;
    const int m4_lo = tid & 7;
    #pragma unroll
    for (int i = 0; i < 4; i++) {
        const int m4l = m4_lo + 8 * i;                 // float4 idx within tile
        const int m4g = (m0 >> 2) + m4l;
        if (m4g < MF4) {
            const int me = 4 * m4l;
            const float4 bv = reinterpret_cast<const float4*>(bias)[m4g];
            float4 r;
            r.x = tile[b_st][me + 0] + bv.x;
            r.y = tile[b_st][me + 1] + bv.y;
            r.z = tile[b_st][me + 2] + bv.z;
            r.w = tile[b_st][me + 3] + bv.w;
            reinterpret_cast<float4*>(out)[(size_t)b_st * MF4 + m4g] = r;
        }
    }
}

extern "C" void kernel_launch(void* const* d_in, const int* in_sizes, int n_in,
                              void* d_out, int out_size) {
    const float* x       = (const float*)d_in[0];   // (B, N, 1)
    const int*   indices = (const int*)  d_in[1];   // (2, NNZ)
    const float* values  = (const float*)d_in[2];   // (NNZ,)
    const float* bias    = (const float*)d_in[3];   // (M, 1)
    float*       out     = (float*)d_out;           // (B, M, 1)

    (void)in_sizes; (void)n_in; (void)out_size;

    {   // 1) transpose x -> xt, zero yt. 128 n per block.
        const int blocks = (NF4 + 31) / 32;            // 782
        k_transpose_in<<<blocks, 256>>>(x);
    }
    {   // 2) edge scatter: exactly NNZ * 8 threads = 100000 blocks x 256
        k_scatter<<<(int)((long long)NNZ * 8 / 256), 256>>>(indices, values);
    }
    {   // 3) transpose yt -> out (+bias). 128 m per block.
        const int blocks = (MF4 + 31) / 32;            // 782
        k_transpose_out<<<blocks, 256>>>(out, bias);
    }
}

// round 15
// speedup vs baseline: 1.4667x; 1.0247x over previous
#include <cuda_runtime.h>

// x (B,N,1) f32, indices (2,NNZ) i32, values (NNZ,) f32, bias (M,1) f32
//   -> out (B,M,1) f32
#define NN   100000
#define MM   100000
#define NNZ  3200000
#define BB   32
#define NF4  (NN / 4)          // 25000 float4 per batch row
#define MF4  (MM / 4)

// Scratch in batch-contiguous layout:
// xt[n*32 + b] = x[b*N + n];  yt[m*32 + b] accumulates, then transposed out.
__device__ float g_xt[(size_t)NN * BB];
__device__ float g_yt[(size_t)MM * BB];

// ---------------------------------------------------------------------------
// Kernel 1: transpose x (B,N) -> xt (N,B), zero yt. float4 both global sides.
// Tile: 32 b-rows x 128 n-cols, 256 threads. The yt zeroing is hoisted into
// the load phase so its L2 writes overlap the DRAM load latency.
// ---------------------------------------------------------------------------
__global__ void k_transpose_in(const float* __restrict__ x) {
    __shared__ float tile[128][33];
    const int tid = threadIdx.x;
    const int c4_base = blockIdx.x * 32;       // float4 column base
    const int n0 = c4_base * 4;                // element column base

    // Load phase: thread owns b = tid>>3, float4 column c4 = (tid&7) + 8i.
    const int b_ld  = tid >> 3;
    const int c4_lo = tid & 7;
    #pragma unroll
    for (int i = 0; i < 4; i++) {
        const int c4l = c4_lo + 8 * i;                 // 0..31 within tile
        const int c4g = c4_base + c4l;
        if (c4g < NF4) {
            const float4 v =
                reinterpret_cast<const float4*>(x)[(size_t)b_ld * NF4 + c4g];
            tile[4 * c4l + 0][b_ld] = v.x;
            tile[4 * c4l + 1][b_ld] = v.y;
            tile[4 * c4l + 2][b_ld] = v.z;
            tile[4 * c4l + 3][b_ld] = v.w;
        }
        // Independent work under load latency: zero yt slots for this tile.
        const int k  = tid + 256 * i;                  // 0..1023 = 128 n x 8 b4
        const int nz = n0 + (k >> 3);
        if (nz < NN) {
            reinterpret_cast<float4*>(g_yt)[(size_t)nz * 8 + (k & 7)] =
                make_float4(0.f, 0.f, 0.f, 0.f);
        }
    }
    __syncthreads();

    // Store phase: thread owns n_local = (tid>>3) + 32i, batch-quad b4 = tid&7.
    const int b4 = tid & 7;
    #pragma unroll
    for (int i = 0; i < 4; i++) {
        const int nl = (tid >> 3) + 32 * i;            // 0..127
        const int n  = n0 + nl;
        if (n < NN) {
            float4 v;
            v.x = tile[nl][4 * b4 + 0];
            v.y = tile[nl][4 * b4 + 1];
            v.z = tile[nl][4 * b4 + 2];
            v.w = tile[nl][4 * b4 + 3];
            reinterpret_cast<float4*>(g_xt)[(size_t)n * 8 + b4] = v;
        }
    }
}

// ---------------------------------------------------------------------------
// Kernel 2: edge scatter — the proven optimum (R3/R9/R10; six alternative
// shapes regressed; runs AT the measured LTS byte cap). 8 threads per edge;
// one coalesced 128B float4 gather, one red.global.add.v4.f32. Grid exact:
// NNZ*8 == 100000 blocks * 256, no guard needed. UNTOUCHED.
// ---------------------------------------------------------------------------
__global__ void k_scatter(const int* __restrict__ indices,
                          const float* __restrict__ values) {
    const long long t = (long long)blockIdx.x * blockDim.x + threadIdx.x;
    const long long e = t >> 3;        // edge id (< NNZ by construction)
    const int       q = (int)(t & 7);  // which float4 of the 32 batches

    const int   src = indices[e];
    const int   dst = indices[(long long)NNZ + e];
    const float v   = values[e];

    const float4 xv = reinterpret_cast<const float4*>(g_xt)[(size_t)src * 8 + q];
    const float4 c  = make_float4(v * xv.x, v * xv.y, v * xv.z, v * xv.w);

    float4* p = reinterpret_cast<float4*>(g_yt) + (size_t)dst * 8 + q;
    asm volatile("red.global.add.v4.f32 [%0], {%1, %2, %3, %4};"
                 :: "l"(p), "f"(c.x), "f"(c.y), "f"(c.z), "f"(c.w)
                 : "memory");
}

// ---------------------------------------------------------------------------
// Kernel 3: transpose yt (M,B) -> out (B,M) + bias. float4 both sides.
// Tile: 128 m x 32 b; pitch-129 smem. Bias loads hoisted above the barrier
// so they fly during the yt-read wave.
// ---------------------------------------------------------------------------
__global__ void k_transpose_out(float* __restrict__ out,
                                const float* __restrict__ bias) {
    __shared__ float tile[32][129];
    const int tid = threadIdx.x;
    const int m0 = blockIdx.x * 128;

    // Hoisted: the 4 bias float4 loads this thread needs in the store phase.
    const int m4_lo = tid & 7;
    float4 bv[4];
    #pragma unroll
    for (int i = 0; i < 4; i++) {
        const int m4g = (m0 >> 2) + m4_lo + 8 * i;
        bv[i] = (m4g < MF4) ? reinterpret_cast<const float4*>(bias)[m4g]
                            : make_float4(0.f, 0.f, 0.f, 0.f);
    }

    // Load phase: thread owns m_local = (tid>>3) + 32i, b4 = tid&7.
    const int b4 = tid & 7;
    #pragma unroll
    for (int i = 0; i < 4; i++) {
        const int ml = (tid >> 3) + 32 * i;            // 0..127
        const int m  = m0 + ml;
        if (m < MM) {
            const float4 v =
                reinterpret_cast<const float4*>(g_yt)[(size_t)m * 8 + b4];
            tile[4 * b4 + 0][ml] = v.x;
            tile[4 * b4 + 1][ml] = v.y;
            tile[4 * b4 + 2][ml] = v.z;
            tile[4 * b4 + 3][ml] = v.w;
        }
    }
    __syncthreads();

    // Store phase: thread owns b = tid>>3, m4 = (tid&7) + 8i.
    const int b_st = tid >> 3;
    #pragma unroll
    for (int i = 0; i < 4; i++) {
        const int m4l = m4_lo + 8 * i;                 // float4 idx within tile
        const int m4g = (m0 >> 2) + m4l;
        if (m4g < MF4) {
            const int me = 4 * m4l;
            float4 r;
            r.x = tile[b_st][me + 0] + bv[i].x;
            r.y = tile[b_st][me + 1] + bv[i].y;
            r.z = tile[b_st][me + 2] + bv[i].z;
            r.w = tile[b_st][me + 3] + bv[i].w;
            reinterpret_cast<float4*>(out)[(size_t)b_st * MF4 + m4g] = r;
        }
    }
}

extern "C" void kernel_launch(void* const* d_in, const int* in_sizes, int n_in,
                              void* d_out, int out_size) {
    const float* x       = (const float*)d_in[0];   // (B, N, 1)
    const int*   indices = (const int*)  d_in[1];   // (2, NNZ)
    const float* values  = (const float*)d_in[2];   // (NNZ,)
    const float* bias    = (const float*)d_in[3];   // (M, 1)
    float*       out     = (float*)d_out;           // (B, M, 1)

    (void)in_sizes; (void)n_in; (void)out_size;

    {   // 1) transpose x -> xt, zero yt (zeroing overlapped with loads)
        const int blocks = (NF4 + 31) / 32;            // 782
        k_transpose_in<<<blocks, 256>>>(x);
    }
    {   // 2) edge scatter: exactly NNZ * 8 threads = 100000 blocks x 256
        k_scatter<<<(int)((long long)NNZ * 8 / 256), 256>>>(indices, values);
    }
    {   // 3) transpose yt -> out (+bias, hoisted)
        const int blocks = (MF4 + 31) / 32;            // 782
        k_transpose_out<<<blocks, 256>>>(out, bias);
    }
}